// round 7
// baseline (speedup 1.0000x reference)
#include <cuda_runtime.h>
#include <cstdint>

#define S_DIM 128
#define N_DIM 256
#define CM 256
#define CH 32
#define CZ 128
#define P_DIM 8192
#define LN_EPS 1e-5f
#define OPM_EPS 1e-3f

__device__ __align__(16) float g_a[P_DIM * S_DIM];          // [p=(n,h)][s] tf32-rounded
__device__ __align__(16) float g_b[P_DIM * S_DIM];          // [q=(n,h)][s] tf32-rounded
__device__ __align__(16) float g_O[(size_t)P_DIM * P_DIM];  // [(i,c)][(j,d)] tf32-rounded
__device__ __align__(16) float g_woT[CZ * CH * CH];         // [z][k=(c,d)] tf32-rounded
__device__ float g_norm[N_DIM * N_DIM];

__device__ __forceinline__ uint32_t rna_tf32(float x) {
    uint32_t r;
    asm("cvt.rna.tf32.f32 %0, %1;" : "=r"(r) : "f"(x));
    return r;
}
__device__ __forceinline__ uint32_t smem_u32(const void* p) {
    uint32_t a;
    asm("{ .reg .u64 t; cvta.to.shared.u64 t, %1; cvt.u32.u64 %0, t; }" : "=r"(a) : "l"(p));
    return a;
}
__device__ __forceinline__ void mma_tf32(float* c, const uint32_t* a, const uint32_t* b) {
    asm volatile(
        "mma.sync.aligned.m16n8k8.row.col.f32.tf32.tf32.f32 "
        "{%0,%1,%2,%3}, {%4,%5,%6,%7}, {%8,%9}, {%0,%1,%2,%3};\n"
        : "+f"(c[0]), "+f"(c[1]), "+f"(c[2]), "+f"(c[3])
        : "r"(a[0]), "r"(a[1]), "r"(a[2]), "r"(a[3]), "r"(b[0]), "r"(b[1]));
}
__device__ __forceinline__ void ldsm_x4(uint32_t* r, uint32_t addr) {
    asm volatile("ldmatrix.sync.aligned.m8n8.x4.shared.b16 {%0,%1,%2,%3}, [%4];"
        : "=r"(r[0]), "=r"(r[1]), "=r"(r[2]), "=r"(r[3]) : "r"(addr));
}
__device__ __forceinline__ void cp16(uint32_t d, const float* s) {
    asm volatile("cp.async.cg.shared.global [%0], [%1], 16;" :: "r"(d), "l"(s));
}
#define CP_COMMIT() asm volatile("cp.async.commit_group;" ::: "memory")
#define CP_WAIT1()  asm volatile("cp.async.wait_group 1;" ::: "memory")

// Stage: [regionA | regionB], 384 padded rows of 36 floats = 55296 B, 3 stages.
#define ROW_BYTES   144u
#define STAGE_BYTES 55296u
#define SMEM_BYTES  (3 * 55296)

// 64x64 warp tile, one 32-K chunk: 8 ldmatrix.x4 feed 32 MMAs per kk-step
__device__ __forceinline__ void mma_chunk(uint32_t a_base, uint32_t b_base,
                                          float acc[4][8][4]) {
    #pragma unroll
    for (int kk = 0; kk < 4; kk++) {
        uint32_t af[4][4], bf[8][2];
        #pragma unroll
        for (int mt = 0; mt < 4; mt++)
            ldsm_x4(af[mt], a_base + kk * 32 + mt * (16 * ROW_BYTES));
        #pragma unroll
        for (int pr = 0; pr < 4; pr++) {
            uint32_t t[4];
            ldsm_x4(t, b_base + kk * 32 + pr * (16 * ROW_BYTES));
            bf[2 * pr][0] = t[0]; bf[2 * pr][1] = t[1];
            bf[2 * pr + 1][0] = t[2]; bf[2 * pr + 1][1] = t[3];
        }
        #pragma unroll
        for (int mt = 0; mt < 4; mt++)
            #pragma unroll
            for (int nt = 0; nt < 8; nt++)
                mma_tf32(acc[mt][nt], af[mt], bf[nt]);
    }
}

// ============================================================================
// Kernel 1: LayerNorm + dual 256->32 projection (weights cached in smem).
// ============================================================================
__global__ void __launch_bounds__(256) ln_proj_kernel(
        const float* __restrict__ m, const float* __restrict__ mask,
        const float* __restrict__ ln_w, const float* __restrict__ ln_b,
        const float* __restrict__ w1, const float* __restrict__ b1,
        const float* __restrict__ w2, const float* __restrict__ b2) {
    extern __shared__ __align__(16) float dsm[];
    float* sw1 = dsm;              // [256][32]
    float* sw2 = dsm + 8192;       // [256][32]
    float* sh_ln = dsm + 16384;    // [256]
    float* part = dsm + 16640;     // [4][64]
    __shared__ float wsum[8], wsum2[8], s_stats[2];

    const int s = blockIdx.x >> 4;
    const int grp = blockIdx.x & 15;
    const int tid = threadIdx.x;

    #pragma unroll
    for (int i = 0; i < 8; i++) {
        int f = tid + i * 256;
        *(float4*)&sw1[f * 4] = *(const float4*)&w1[f * 4];
        *(float4*)&sw2[f * 4] = *(const float4*)&w2[f * 4];
    }
    __syncthreads();

    const int g = tid >> 6, o = tid & 63, h = o & 31;
    const float* wsm = (o < 32) ? sw1 : sw2;
    const int k0 = g * 64;

    for (int r = 0; r < 16; r++) {
        const int n = grp * 16 + r;
        const int row = s * N_DIM + n;
        float x = m[(size_t)row * CM + tid];
        float v = x, v2 = x * x;
        #pragma unroll
        for (int off = 16; off > 0; off >>= 1) {
            v  += __shfl_xor_sync(0xffffffff, v,  off);
            v2 += __shfl_xor_sync(0xffffffff, v2, off);
        }
        if ((tid & 31) == 0) { wsum[tid >> 5] = v; wsum2[tid >> 5] = v2; }
        __syncthreads();
        if (tid == 0) {
            float t = 0.f, t2 = 0.f;
            #pragma unroll
            for (int i = 0; i < 8; i++) { t += wsum[i]; t2 += wsum2[i]; }
            float mu = t * (1.f / CM);
            float var = t2 * (1.f / CM) - mu * mu;
            s_stats[0] = mu; s_stats[1] = rsqrtf(var + LN_EPS);
        }
        __syncthreads();
        sh_ln[tid] = (x - s_stats[0]) * s_stats[1] * ln_w[tid] + ln_b[tid];
        __syncthreads();

        float acc = 0.f;
        #pragma unroll 16
        for (int k = k0; k < k0 + 64; k++)
            acc += sh_ln[k] * wsm[k * CH + h];
        part[g * 64 + o] = acc;
        __syncthreads();

        if (tid < 64) {
            float mk = mask[row];
            float sum = part[tid] + part[64 + tid] + part[128 + tid] + part[192 + tid];
            if (tid < 32)
                g_a[(size_t)(n * CH + tid) * S_DIM + s] =
                    __uint_as_float(rna_tf32((sum + b1[tid]) * mk));
            else
                g_b[(size_t)(n * CH + h) * S_DIM + s] =
                    __uint_as_float(rna_tf32((sum + b2[h]) * mk));
        }
        __syncthreads();
    }
}

// ============================================================================
// norm + woT
// ============================================================================
__global__ void norm_kernel(const float* __restrict__ mask) {
    const int i = blockIdx.x, j = threadIdx.x;
    __shared__ float mi[S_DIM];
    if (j < S_DIM) mi[j] = mask[j * N_DIM + i];
    __syncthreads();
    float acc = 0.f;
    #pragma unroll 8
    for (int s = 0; s < S_DIM; s++) acc += mi[s] * mask[s * N_DIM + j];
    g_norm[i * N_DIM + j] = acc + OPM_EPS;
}

__global__ void woT_kernel(const float* __restrict__ wo) {
    int idx = blockIdx.x * 256 + threadIdx.x;   // 131072
    int z = idx >> 10, k = idx & 1023;
    g_woT[idx] = __uint_as_float(rna_tf32(wo[k * CZ + z]));
}

// ============================================================================
// GEMM1: O[8192,8192] = A[8192,128]*B[8192,128]^T.
// CTA tile 128(M) x 256(N), 8 warps 2x4 of 64x64, cp.async 3-stage, 4 chunks.
// Stage: A 128 rows @0, B 256 rows @ 128*ROW_BYTES.
// ============================================================================
__global__ void __launch_bounds__(256) gemm1_mma() {
    extern __shared__ __align__(16) float sm[];
    const uint32_t sbase = smem_u32(sm);
    const int tid = threadIdx.x, wid = tid >> 5, lane = tid & 31;
    const int wm = (wid & 1) * 64, wn = (wid >> 1) * 64;
    const int p0 = blockIdx.y * 128, q0 = blockIdx.x * 256;
    const int lg = lane >> 3, lrow = lane & 7;
    const uint32_t B_OFF = 128u * ROW_BYTES;   // 18432
    const uint32_t a_lo = (uint32_t)(wm + (lg & 1) * 8 + lrow) * ROW_BYTES
                        + (uint32_t)(lg >> 1) * 16;
    const uint32_t b_lo = B_OFF + (uint32_t)(wn + (lg >> 1) * 8 + lrow) * ROW_BYTES
                        + (uint32_t)(lg & 1) * 16;

    float acc[4][8][4];
    #pragma unroll
    for (int a = 0; a < 4; a++)
        #pragma unroll
        for (int b = 0; b < 8; b++)
            #pragma unroll
            for (int e = 0; e < 4; e++) acc[a][b][e] = 0.f;

    auto copy1 = [&](int ch, int st) {
        const int kb = ch * 32;
        const uint32_t dA = sbase + st * STAGE_BYTES;
        const uint32_t dB = dA + B_OFF;
        #pragma unroll
        for (int i = 0; i < 4; i++) {        // A: 128 rows x 8 chunks
            int f = tid + i * 256, rr = f >> 3, cc = f & 7;
            cp16(dA + rr * ROW_BYTES + cc * 16,
                 &g_a[(size_t)(p0 + rr) * S_DIM + kb + cc * 4]);
        }
        #pragma unroll
        for (int i = 0; i < 8; i++) {        // B: 256 rows x 8 chunks
            int f = tid + i * 256, rr = f >> 3, cc = f & 7;
            cp16(dB + rr * ROW_BYTES + cc * 16,
                 &g_b[(size_t)(q0 + rr) * S_DIM + kb + cc * 4]);
        }
    };

    copy1(0, 0); CP_COMMIT();
    copy1(1, 1); CP_COMMIT();

    #pragma unroll
    for (int ch = 0; ch < 4; ch++) {
        CP_WAIT1();
        __syncthreads();
        const uint32_t so = sbase + (uint32_t)(ch % 3) * STAGE_BYTES;
        mma_chunk(so + a_lo, so + b_lo, acc);
        if (ch + 2 < 4) copy1(ch + 2, (ch + 2) % 3);
        CP_COMMIT();
    }

    // epilogue -> g_O (tf32-rounded)
    #pragma unroll
    for (int mt = 0; mt < 4; mt++) {
        const int row0 = p0 + wm + mt * 16 + (lane >> 2);
        #pragma unroll
        for (int nt = 0; nt < 8; nt++) {
            const int col = q0 + wn + nt * 8 + (lane & 3) * 2;
            float2 v0, v1;
            v0.x = __uint_as_float(rna_tf32(acc[mt][nt][0]));
            v0.y = __uint_as_float(rna_tf32(acc[mt][nt][1]));
            v1.x = __uint_as_float(rna_tf32(acc[mt][nt][2]));
            v1.y = __uint_as_float(rna_tf32(acc[mt][nt][3]));
            *(float2*)&g_O[(size_t)row0 * P_DIM + col]       = v0;
            *(float2*)&g_O[(size_t)(row0 + 8) * P_DIM + col] = v1;
        }
    }
}

// ============================================================================
// GEMM2: out[65536,128] = O'[65536,1024] @ woT^T (+bo, /norm).
// CTA tile 256(M) x 128(N) -> one CTA = one full i row-block; A chunk is a
// CONTIGUOUS 32KB strip of g_O. 8 warps 4x2 of 64x64, 3-stage, 32 chunks.
// Stage: A 256 rows @0, B 128 rows @ 256*ROW_BYTES.
// ============================================================================
__global__ void __launch_bounds__(256) gemm2_mma(const float* __restrict__ bo,
                                                 float* __restrict__ out) {
    extern __shared__ __align__(16) float sm[];
    const uint32_t sbase = smem_u32(sm);
    const int tid = threadIdx.x, wid = tid >> 5, lane = tid & 31;
    const int wm = (wid & 3) * 64, wn = (wid >> 2) * 64;
    const int m0 = blockIdx.x * 256;
    const int i_idx = blockIdx.x;
    const int lg = lane >> 3, lrow = lane & 7;
    const uint32_t B_OFF = 256u * ROW_BYTES;   // 36864
    const uint32_t a_lo = (uint32_t)(wm + (lg & 1) * 8 + lrow) * ROW_BYTES
                        + (uint32_t)(lg >> 1) * 16;
    const uint32_t b_lo = B_OFF + (uint32_t)(wn + (lg >> 1) * 8 + lrow) * ROW_BYTES
                        + (uint32_t)(lg & 1) * 16;

    float acc[4][8][4];
    #pragma unroll
    for (int a = 0; a < 4; a++)
        #pragma unroll
        for (int b = 0; b < 8; b++)
            #pragma unroll
            for (int e = 0; e < 4; e++) acc[a][b][e] = 0.f;

    auto copy1 = [&](int ch, int st) {
        const float* gA = &g_O[((size_t)(i_idx * 32 + ch)) * P_DIM];
        const uint32_t dA = sbase + st * STAGE_BYTES;
        const uint32_t dB = dA + B_OFF;
        #pragma unroll
        for (int i = 0; i < 8; i++) {        // A: 256 rows
            int f = tid + i * 256, rr = f >> 3, cc = f & 7;
            cp16(dA + rr * ROW_BYTES + cc * 16, &gA[f * 4]);
        }
        #pragma unroll
        for (int i = 0; i < 4; i++) {        // B: 128 rows (woT)
            int f = tid + i * 256, rr = f >> 3, cc = f & 7;
            cp16(dB + rr * ROW_BYTES + cc * 16,
                 &g_woT[(size_t)rr * 1024 + ch * 32 + cc * 4]);
        }
    };

    copy1(0, 0); CP_COMMIT();
    copy1(1, 1); CP_COMMIT();

    int st = 0;
    for (int ch = 0; ch < 32; ch++) {
        CP_WAIT1();
        __syncthreads();
        const uint32_t so = sbase + (uint32_t)st * STAGE_BYTES;
        mma_chunk(so + a_lo, so + b_lo, acc);
        if (ch + 2 < 32) {
            int ns = st + 2; if (ns >= 3) ns -= 3;
            copy1(ch + 2, ns);
        }
        CP_COMMIT();
        if (++st == 3) st = 0;
    }

    // epilogue: +bo, /norm
    #pragma unroll
    for (int mt = 0; mt < 4; mt++) {
        const int row0 = m0 + wm + mt * 16 + (lane >> 2);
        const float inv0 = 1.0f / g_norm[row0];
        const float inv1 = 1.0f / g_norm[row0 + 8];
        #pragma unroll
        for (int nt = 0; nt < 8; nt++) {
            const int col = wn + nt * 8 + (lane & 3) * 2;
            const float b0v = bo[col], b1v = bo[col + 1];
            float2 v0, v1;
            v0.x = (acc[mt][nt][0] + b0v) * inv0;
            v0.y = (acc[mt][nt][1] + b1v) * inv0;
            v1.x = (acc[mt][nt][2] + b0v) * inv1;
            v1.y = (acc[mt][nt][3] + b1v) * inv1;
            *(float2*)&out[(size_t)row0 * CZ + col]       = v0;
            *(float2*)&out[(size_t)(row0 + 8) * CZ + col] = v1;
        }
    }
}

// ============================================================================
extern "C" void kernel_launch(void* const* d_in, const int* in_sizes, int n_in,
                              void* d_out, int out_size) {
    const float* m    = (const float*)d_in[0];
    const float* mask = (const float*)d_in[1];
    const float* ln_w = (const float*)d_in[2];
    const float* ln_b = (const float*)d_in[3];
    const float* w1   = (const float*)d_in[4];
    const float* b1   = (const float*)d_in[5];
    const float* w2   = (const float*)d_in[6];
    const float* b2   = (const float*)d_in[7];
    const float* wo   = (const float*)d_in[8];
    const float* bo   = (const float*)d_in[9];
    float* out = (float*)d_out;

    cudaFuncSetAttribute(ln_proj_kernel, cudaFuncAttributeMaxDynamicSharedMemorySize, 67584);
    cudaFuncSetAttribute(gemm1_mma, cudaFuncAttributeMaxDynamicSharedMemorySize, SMEM_BYTES);
    cudaFuncSetAttribute(gemm2_mma, cudaFuncAttributeMaxDynamicSharedMemorySize, SMEM_BYTES);

    ln_proj_kernel<<<2048, 256, 67584>>>(m, mask, ln_w, ln_b, w1, b1, w2, b2);
    norm_kernel<<<N_DIM, 256>>>(mask);
    woT_kernel<<<512, 256>>>(wo);

    dim3 g1(32, 64);   // x: N/256, y: M/128
    gemm1_mma<<<g1, 256, SMEM_BYTES>>>();
    gemm2_mma<<<256, 256, SMEM_BYTES>>>(bo, out);
}

// round 8
// speedup vs baseline: 1.0273x; 1.0273x over previous
#include <cuda_runtime.h>
#include <cstdint>

#define S_DIM 128
#define N_DIM 256
#define CM 256
#define CH 32
#define CZ 128
#define P_DIM 8192
#define LN_EPS 1e-5f
#define OPM_EPS 1e-3f

__device__ __align__(16) float g_a[P_DIM * S_DIM];          // [p=(n,h)][s] tf32-rounded
__device__ __align__(16) float g_b[P_DIM * S_DIM];          // [q=(n,h)][s] tf32-rounded
__device__ __align__(16) float g_O[(size_t)P_DIM * P_DIM];  // [(i,c)][(j,d)] tf32-rounded
__device__ __align__(16) float g_woT[CZ * CH * CH];         // [z][k=(c,d)] tf32-rounded
__device__ float g_norm[N_DIM * N_DIM];

__device__ __forceinline__ uint32_t rna_tf32(float x) {
    uint32_t r;
    asm("cvt.rna.tf32.f32 %0, %1;" : "=r"(r) : "f"(x));
    return r;
}
__device__ __forceinline__ uint32_t smem_u32(const void* p) {
    uint32_t a;
    asm("{ .reg .u64 t; cvta.to.shared.u64 t, %1; cvt.u32.u64 %0, t; }" : "=r"(a) : "l"(p));
    return a;
}
__device__ __forceinline__ void mma_tf32(float* c, const uint32_t* a, const uint32_t* b) {
    asm volatile(
        "mma.sync.aligned.m16n8k8.row.col.f32.tf32.tf32.f32 "
        "{%0,%1,%2,%3}, {%4,%5,%6,%7}, {%8,%9}, {%0,%1,%2,%3};\n"
        : "+f"(c[0]), "+f"(c[1]), "+f"(c[2]), "+f"(c[3])
        : "r"(a[0]), "r"(a[1]), "r"(a[2]), "r"(a[3]), "r"(b[0]), "r"(b[1]));
}
__device__ __forceinline__ void ldsm_x4(uint32_t* r, uint32_t addr) {
    asm volatile("ldmatrix.sync.aligned.m8n8.x4.shared.b16 {%0,%1,%2,%3}, [%4];"
        : "=r"(r[0]), "=r"(r[1]), "=r"(r[2]), "=r"(r[3]) : "r"(addr));
}
__device__ __forceinline__ void cp16(uint32_t d, const float* s) {
    asm volatile("cp.async.cg.shared.global [%0], [%1], 16;" :: "r"(d), "l"(s));
}
#define CP_COMMIT() asm volatile("cp.async.commit_group;" ::: "memory")
#define CP_WAIT1()  asm volatile("cp.async.wait_group 1;" ::: "memory")

// Stage layout (floats): [A 128x36 | B 128x36] per stage, 3 stages.
#define ROW_BYTES   144u
#define STAGE_BYTES 36864u
#define B_OFF       18432u
#define SMEM_BYTES  (3 * 36864)

// load all fragments of one kk-step (8 ldmatrix.x4)
__device__ __forceinline__ void load_frags(uint32_t a_base, uint32_t b_base, int kk,
                                           uint32_t af[4][4], uint32_t bf[8][2]) {
    #pragma unroll
    for (int mt = 0; mt < 4; mt++)
        ldsm_x4(af[mt], a_base + kk * 32 + mt * (16 * ROW_BYTES));
    #pragma unroll
    for (int pr = 0; pr < 4; pr++) {
        uint32_t t[4];
        ldsm_x4(t, b_base + kk * 32 + pr * (16 * ROW_BYTES));
        bf[2 * pr][0] = t[0]; bf[2 * pr][1] = t[1];
        bf[2 * pr + 1][0] = t[2]; bf[2 * pr + 1][1] = t[3];
    }
}

// one 32-K chunk of a 64x64 warp tile, register-double-buffered fragments:
// kk+1's LDSMs issue before kk's MMAs so LDS latency hides under tensor work.
__device__ __forceinline__ void mma_chunk(uint32_t a_base, uint32_t b_base,
                                          float acc[4][8][4]) {
    uint32_t af[2][4][4], bf[2][8][2];
    load_frags(a_base, b_base, 0, af[0], bf[0]);
    #pragma unroll
    for (int kk = 0; kk < 4; kk++) {
        const int cur = kk & 1;
        if (kk < 3)
            load_frags(a_base, b_base, kk + 1, af[cur ^ 1], bf[cur ^ 1]);
        #pragma unroll
        for (int mt = 0; mt < 4; mt++)
            #pragma unroll
            for (int nt = 0; nt < 8; nt++)
                mma_tf32(acc[mt][nt], af[cur][mt], bf[cur][nt]);
    }
}

// ============================================================================
// Kernel 1: LayerNorm + dual 256->32 projection (weights cached in smem).
// ============================================================================
__global__ void __launch_bounds__(256) ln_proj_kernel(
        const float* __restrict__ m, const float* __restrict__ mask,
        const float* __restrict__ ln_w, const float* __restrict__ ln_b,
        const float* __restrict__ w1, const float* __restrict__ b1,
        const float* __restrict__ w2, const float* __restrict__ b2) {
    extern __shared__ __align__(16) float dsm[];
    float* sw1 = dsm;              // [256][32]
    float* sw2 = dsm + 8192;       // [256][32]
    float* sh_ln = dsm + 16384;    // [256]
    float* part = dsm + 16640;     // [4][64]
    __shared__ float wsum[8], wsum2[8], s_stats[2];

    const int s = blockIdx.x >> 4;
    const int grp = blockIdx.x & 15;
    const int tid = threadIdx.x;

    #pragma unroll
    for (int i = 0; i < 8; i++) {
        int f = tid + i * 256;
        *(float4*)&sw1[f * 4] = *(const float4*)&w1[f * 4];
        *(float4*)&sw2[f * 4] = *(const float4*)&w2[f * 4];
    }
    __syncthreads();

    const int g = tid >> 6, o = tid & 63, h = o & 31;
    const float* wsm = (o < 32) ? sw1 : sw2;
    const int k0 = g * 64;

    for (int r = 0; r < 16; r++) {
        const int n = grp * 16 + r;
        const int row = s * N_DIM + n;
        float x = m[(size_t)row * CM + tid];
        float v = x, v2 = x * x;
        #pragma unroll
        for (int off = 16; off > 0; off >>= 1) {
            v  += __shfl_xor_sync(0xffffffff, v,  off);
            v2 += __shfl_xor_sync(0xffffffff, v2, off);
        }
        if ((tid & 31) == 0) { wsum[tid >> 5] = v; wsum2[tid >> 5] = v2; }
        __syncthreads();
        if (tid == 0) {
            float t = 0.f, t2 = 0.f;
            #pragma unroll
            for (int i = 0; i < 8; i++) { t += wsum[i]; t2 += wsum2[i]; }
            float mu = t * (1.f / CM);
            float var = t2 * (1.f / CM) - mu * mu;
            s_stats[0] = mu; s_stats[1] = rsqrtf(var + LN_EPS);
        }
        __syncthreads();
        sh_ln[tid] = (x - s_stats[0]) * s_stats[1] * ln_w[tid] + ln_b[tid];
        __syncthreads();

        float acc = 0.f;
        #pragma unroll 16
        for (int k = k0; k < k0 + 64; k++)
            acc += sh_ln[k] * wsm[k * CH + h];
        part[g * 64 + o] = acc;
        __syncthreads();

        if (tid < 64) {
            float mk = mask[row];
            float sum = part[tid] + part[64 + tid] + part[128 + tid] + part[192 + tid];
            if (tid < 32)
                g_a[(size_t)(n * CH + tid) * S_DIM + s] =
                    __uint_as_float(rna_tf32((sum + b1[tid]) * mk));
            else
                g_b[(size_t)(n * CH + h) * S_DIM + s] =
                    __uint_as_float(rna_tf32((sum + b2[h]) * mk));
        }
        __syncthreads();
    }
}

// ============================================================================
// norm + woT
// ============================================================================
__global__ void norm_kernel(const float* __restrict__ mask) {
    const int i = blockIdx.x, j = threadIdx.x;
    __shared__ float mi[S_DIM];
    if (j < S_DIM) mi[j] = mask[j * N_DIM + i];
    __syncthreads();
    float acc = 0.f;
    #pragma unroll 8
    for (int s = 0; s < S_DIM; s++) acc += mi[s] * mask[s * N_DIM + j];
    g_norm[i * N_DIM + j] = acc + OPM_EPS;
}

__global__ void woT_kernel(const float* __restrict__ wo) {
    int idx = blockIdx.x * 256 + threadIdx.x;   // 131072
    int z = idx >> 10, k = idx & 1023;
    g_woT[idx] = __uint_as_float(rna_tf32(wo[k * CZ + z]));
}

// ============================================================================
// GEMM1: O[8192,8192] = A[8192,128]*B[8192,128]^T.  128x128 CTA, 4 warps,
// 64x64 warp tiles, cp.async 3-stage pipeline, NC=4 chunks.
// ============================================================================
__global__ void __launch_bounds__(128) gemm1_mma() {
    extern __shared__ __align__(16) float sm[];
    const uint32_t sbase = smem_u32(sm);
    const int tid = threadIdx.x, wid = tid >> 5, lane = tid & 31;
    const int wm = (wid & 1) * 64, wn = (wid >> 1) * 64;
    const int p0 = blockIdx.y * 128, q0 = blockIdx.x * 128;
    const int lg = lane >> 3, lrow = lane & 7;
    const uint32_t a_lo = (uint32_t)(wm + (lg & 1) * 8 + lrow) * ROW_BYTES
                        + (uint32_t)(lg >> 1) * 16;
    const uint32_t b_lo = B_OFF + (uint32_t)(wn + (lg >> 1) * 8 + lrow) * ROW_BYTES
                        + (uint32_t)(lg & 1) * 16;

    float acc[4][8][4];
    #pragma unroll
    for (int a = 0; a < 4; a++)
        #pragma unroll
        for (int b = 0; b < 8; b++)
            #pragma unroll
            for (int e = 0; e < 4; e++) acc[a][b][e] = 0.f;

    auto copy1 = [&](int ch, int st) {
        const int kb = ch * 32;
        const uint32_t dA = sbase + st * STAGE_BYTES;
        const uint32_t dB = dA + B_OFF;
        #pragma unroll
        for (int i = 0; i < 8; i++) {
            int f = tid + i * 128, rr = f >> 3, cc = f & 7;
            cp16(dA + rr * ROW_BYTES + cc * 16,
                 &g_a[(size_t)(p0 + rr) * S_DIM + kb + cc * 4]);
            cp16(dB + rr * ROW_BYTES + cc * 16,
                 &g_b[(size_t)(q0 + rr) * S_DIM + kb + cc * 4]);
        }
    };

    copy1(0, 0); CP_COMMIT();
    copy1(1, 1); CP_COMMIT();

    #pragma unroll
    for (int ch = 0; ch < 4; ch++) {
        CP_WAIT1();
        __syncthreads();
        const uint32_t so = sbase + (uint32_t)(ch % 3) * STAGE_BYTES;
        mma_chunk(so + a_lo, so + b_lo, acc);
        if (ch + 2 < 4) copy1(ch + 2, (ch + 2) % 3);
        CP_COMMIT();
    }

    // epilogue -> g_O (tf32-rounded)
    #pragma unroll
    for (int mt = 0; mt < 4; mt++) {
        const int row0 = p0 + wm + mt * 16 + (lane >> 2);
        #pragma unroll
        for (int nt = 0; nt < 8; nt++) {
            const int col = q0 + wn + nt * 8 + (lane & 3) * 2;
            float2 v0, v1;
            v0.x = __uint_as_float(rna_tf32(acc[mt][nt][0]));
            v0.y = __uint_as_float(rna_tf32(acc[mt][nt][1]));
            v1.x = __uint_as_float(rna_tf32(acc[mt][nt][2]));
            v1.y = __uint_as_float(rna_tf32(acc[mt][nt][3]));
            *(float2*)&g_O[(size_t)row0 * P_DIM + col]       = v0;
            *(float2*)&g_O[(size_t)(row0 + 8) * P_DIM + col] = v1;
        }
    }
}

// ============================================================================
// GEMM2: out[65536,128] = O'[65536,1024] @ woT^T (+bo, /norm).
// 128x128 CTA, 4 warps, 64x64 warp tiles, cp.async 3-stage, NC=32 chunks.
// ============================================================================
__global__ void __launch_bounds__(128) gemm2_mma(const float* __restrict__ bo,
                                                 float* __restrict__ out) {
    extern __shared__ __align__(16) float sm[];
    const uint32_t sbase = smem_u32(sm);
    const int tid = threadIdx.x, wid = tid >> 5, lane = tid & 31;
    const int wm = (wid & 1) * 64, wn = (wid >> 1) * 64;
    const int m0 = blockIdx.x * 128;
    const int i_idx = m0 >> 8, j0 = m0 & 255;
    const int lg = lane >> 3, lrow = lane & 7;
    const uint32_t a_lo = (uint32_t)(wm + (lg & 1) * 8 + lrow) * ROW_BYTES
                        + (uint32_t)(lg >> 1) * 16;
    const uint32_t b_lo = B_OFF + (uint32_t)(wn + (lg >> 1) * 8 + lrow) * ROW_BYTES
                        + (uint32_t)(lg & 1) * 16;

    float acc[4][8][4];
    #pragma unroll
    for (int a = 0; a < 4; a++)
        #pragma unroll
        for (int b = 0; b < 8; b++)
            #pragma unroll
            for (int e = 0; e < 4; e++) acc[a][b][e] = 0.f;

    auto copy1 = [&](int ch, int st) {
        const float* gA = &g_O[((size_t)(i_idx * 32 + ch)) * P_DIM + (size_t)j0 * 32];
        const uint32_t dA = sbase + st * STAGE_BYTES;
        const uint32_t dB = dA + B_OFF;
        #pragma unroll
        for (int i = 0; i < 8; i++) {
            int f = tid + i * 128, rr = f >> 3, cc = f & 7;
            cp16(dA + rr * ROW_BYTES + cc * 16, &gA[f * 4]);
            cp16(dB + rr * ROW_BYTES + cc * 16,
                 &g_woT[(size_t)rr * 1024 + ch * 32 + cc * 4]);
        }
    };

    copy1(0, 0); CP_COMMIT();
    copy1(1, 1); CP_COMMIT();

    int st = 0;
    for (int ch = 0; ch < 32; ch++) {
        CP_WAIT1();
        __syncthreads();
        const uint32_t so = sbase + (uint32_t)st * STAGE_BYTES;
        mma_chunk(so + a_lo, so + b_lo, acc);
        if (ch + 2 < 32) {
            int ns = st + 2; if (ns >= 3) ns -= 3;
            copy1(ch + 2, ns);
        }
        CP_COMMIT();
        if (++st == 3) st = 0;
    }

    // epilogue: +bo, /norm
    #pragma unroll
    for (int mt = 0; mt < 4; mt++) {
        const int row0 = m0 + wm + mt * 16 + (lane >> 2);
        const float inv0 = 1.0f / g_norm[row0];
        const float inv1 = 1.0f / g_norm[row0 + 8];
        #pragma unroll
        for (int nt = 0; nt < 8; nt++) {
            const int col = wn + nt * 8 + (lane & 3) * 2;
            const float b0v = bo[col], b1v = bo[col + 1];
            float2 v0, v1;
            v0.x = (acc[mt][nt][0] + b0v) * inv0;
            v0.y = (acc[mt][nt][1] + b1v) * inv0;
            v1.x = (acc[mt][nt][2] + b0v) * inv1;
            v1.y = (acc[mt][nt][3] + b1v) * inv1;
            *(float2*)&out[(size_t)row0 * CZ + col]       = v0;
            *(float2*)&out[(size_t)(row0 + 8) * CZ + col] = v1;
        }
    }
}

// ============================================================================
extern "C" void kernel_launch(void* const* d_in, const int* in_sizes, int n_in,
                              void* d_out, int out_size) {
    const float* m    = (const float*)d_in[0];
    const float* mask = (const float*)d_in[1];
    const float* ln_w = (const float*)d_in[2];
    const float* ln_b = (const float*)d_in[3];
    const float* w1   = (const float*)d_in[4];
    const float* b1   = (const float*)d_in[5];
    const float* w2   = (const float*)d_in[6];
    const float* b2   = (const float*)d_in[7];
    const float* wo   = (const float*)d_in[8];
    const float* bo   = (const float*)d_in[9];
    float* out = (float*)d_out;

    cudaFuncSetAttribute(ln_proj_kernel, cudaFuncAttributeMaxDynamicSharedMemorySize, 67584);
    cudaFuncSetAttribute(gemm1_mma, cudaFuncAttributeMaxDynamicSharedMemorySize, SMEM_BYTES);
    cudaFuncSetAttribute(gemm2_mma, cudaFuncAttributeMaxDynamicSharedMemorySize, SMEM_BYTES);

    ln_proj_kernel<<<2048, 256, 67584>>>(m, mask, ln_w, ln_b, w1, b1, w2, b2);
    norm_kernel<<<N_DIM, 256>>>(mask);
    woT_kernel<<<512, 256>>>(wo);

    dim3 g1(64, 64);
    gemm1_mma<<<g1, 128, SMEM_BYTES>>>();
    gemm2_mma<<<512, 128, SMEM_BYTES>>>(bo, out);
}

// round 9
// speedup vs baseline: 1.0616x; 1.0334x over previous
#include <cuda_runtime.h>
#include <cstdint>

#define S_DIM 128
#define N_DIM 256
#define CM 256
#define CH 32
#define CZ 128
#define P_DIM 8192
#define LN_EPS 1e-5f
#define OPM_EPS 1e-3f

__device__ __align__(16) float g_a[P_DIM * S_DIM];          // [p=(n,h)][s] tf32-rounded
__device__ __align__(16) float g_b[P_DIM * S_DIM];          // [q=(n,h)][s] tf32-rounded
__device__ __align__(16) float g_O[(size_t)P_DIM * P_DIM];  // [(i,c)][(j,d)] tf32-rounded
__device__ __align__(16) float g_woT[CZ * CH * CH];         // [z][k=(c,d)] tf32-rounded
__device__ float g_norm[N_DIM * N_DIM];

__device__ __forceinline__ uint32_t rna_tf32(float x) {
    uint32_t r;
    asm("cvt.rna.tf32.f32 %0, %1;" : "=r"(r) : "f"(x));
    return r;
}
__device__ __forceinline__ uint32_t smem_u32(const void* p) {
    uint32_t a;
    asm("{ .reg .u64 t; cvta.to.shared.u64 t, %1; cvt.u32.u64 %0, t; }" : "=r"(a) : "l"(p));
    return a;
}
__device__ __forceinline__ void mma_tf32(float* c, const uint32_t* a, const uint32_t* b) {
    asm volatile(
        "mma.sync.aligned.m16n8k8.row.col.f32.tf32.tf32.f32 "
        "{%0,%1,%2,%3}, {%4,%5,%6,%7}, {%8,%9}, {%0,%1,%2,%3};\n"
        : "+f"(c[0]), "+f"(c[1]), "+f"(c[2]), "+f"(c[3])
        : "r"(a[0]), "r"(a[1]), "r"(a[2]), "r"(a[3]), "r"(b[0]), "r"(b[1]));
}
__device__ __forceinline__ void ldsm_x4(uint32_t* r, uint32_t addr) {
    asm volatile("ldmatrix.sync.aligned.m8n8.x4.shared.b16 {%0,%1,%2,%3}, [%4];"
        : "=r"(r[0]), "=r"(r[1]), "=r"(r[2]), "=r"(r[3]) : "r"(addr));
}
__device__ __forceinline__ void cp16(uint32_t d, const float* s) {
    asm volatile("cp.async.cg.shared.global [%0], [%1], 16;" :: "r"(d), "l"(s));
}
#define CP_COMMIT() asm volatile("cp.async.commit_group;" ::: "memory")
#define CP_WAIT1()  asm volatile("cp.async.wait_group 1;" ::: "memory")

// Stage layout (floats): [A 128x36 | B 128x36] per stage, 3 stages.
#define ROW_BYTES   144u
#define STAGE_BYTES 36864u
#define B_OFF       18432u
#define SMEM_BYTES  (3 * 36864)

// 64x32 warp tile, one 32-K chunk: 6 ldmatrix.x4 feed 16 MMAs per kk-step.
__device__ __forceinline__ void mma_chunk(uint32_t a_base, uint32_t b_base,
                                          float acc[4][4][4]) {
    #pragma unroll
    for (int kk = 0; kk < 4; kk++) {
        uint32_t af[4][4], bf[4][2];
        #pragma unroll
        for (int mt = 0; mt < 4; mt++)
            ldsm_x4(af[mt], a_base + kk * 32 + mt * (16 * ROW_BYTES));
        #pragma unroll
        for (int pr = 0; pr < 2; pr++) {
            uint32_t t[4];
            ldsm_x4(t, b_base + kk * 32 + pr * (16 * ROW_BYTES));
            bf[2 * pr][0] = t[0]; bf[2 * pr][1] = t[1];
            bf[2 * pr + 1][0] = t[2]; bf[2 * pr + 1][1] = t[3];
        }
        #pragma unroll
        for (int mt = 0; mt < 4; mt++)
            #pragma unroll
            for (int nt = 0; nt < 4; nt++)
                mma_tf32(acc[mt][nt], af[mt], bf[nt]);
    }
}

// ============================================================================
// Kernel 1: LayerNorm + dual 256->32 projection (weights cached in smem).
// ============================================================================
__global__ void __launch_bounds__(256) ln_proj_kernel(
        const float* __restrict__ m, const float* __restrict__ mask,
        const float* __restrict__ ln_w, const float* __restrict__ ln_b,
        const float* __restrict__ w1, const float* __restrict__ b1,
        const float* __restrict__ w2, const float* __restrict__ b2) {
    extern __shared__ __align__(16) float dsm[];
    float* sw1 = dsm;              // [256][32]
    float* sw2 = dsm + 8192;       // [256][32]
    float* sh_ln = dsm + 16384;    // [256]
    float* part = dsm + 16640;     // [4][64]
    __shared__ float wsum[8], wsum2[8], s_stats[2];

    const int s = blockIdx.x >> 4;
    const int grp = blockIdx.x & 15;
    const int tid = threadIdx.x;

    #pragma unroll
    for (int i = 0; i < 8; i++) {
        int f = tid + i * 256;
        *(float4*)&sw1[f * 4] = *(const float4*)&w1[f * 4];
        *(float4*)&sw2[f * 4] = *(const float4*)&w2[f * 4];
    }
    __syncthreads();

    const int g = tid >> 6, o = tid & 63, h = o & 31;
    const float* wsm = (o < 32) ? sw1 : sw2;
    const int k0 = g * 64;

    for (int r = 0; r < 16; r++) {
        const int n = grp * 16 + r;
        const int row = s * N_DIM + n;
        float x = m[(size_t)row * CM + tid];
        float v = x, v2 = x * x;
        #pragma unroll
        for (int off = 16; off > 0; off >>= 1) {
            v  += __shfl_xor_sync(0xffffffff, v,  off);
            v2 += __shfl_xor_sync(0xffffffff, v2, off);
        }
        if ((tid & 31) == 0) { wsum[tid >> 5] = v; wsum2[tid >> 5] = v2; }
        __syncthreads();
        if (tid == 0) {
            float t = 0.f, t2 = 0.f;
            #pragma unroll
            for (int i = 0; i < 8; i++) { t += wsum[i]; t2 += wsum2[i]; }
            float mu = t * (1.f / CM);
            float var = t2 * (1.f / CM) - mu * mu;
            s_stats[0] = mu; s_stats[1] = rsqrtf(var + LN_EPS);
        }
        __syncthreads();
        sh_ln[tid] = (x - s_stats[0]) * s_stats[1] * ln_w[tid] + ln_b[tid];
        __syncthreads();

        float acc = 0.f;
        #pragma unroll 16
        for (int k = k0; k < k0 + 64; k++)
            acc += sh_ln[k] * wsm[k * CH + h];
        part[g * 64 + o] = acc;
        __syncthreads();

        if (tid < 64) {
            float mk = mask[row];
            float sum = part[tid] + part[64 + tid] + part[128 + tid] + part[192 + tid];
            if (tid < 32)
                g_a[(size_t)(n * CH + tid) * S_DIM + s] =
                    __uint_as_float(rna_tf32((sum + b1[tid]) * mk));
            else
                g_b[(size_t)(n * CH + h) * S_DIM + s] =
                    __uint_as_float(rna_tf32((sum + b2[h]) * mk));
        }
        __syncthreads();
    }
}

// ============================================================================
// norm + woT
// ============================================================================
__global__ void norm_kernel(const float* __restrict__ mask) {
    const int i = blockIdx.x, j = threadIdx.x;
    __shared__ float mi[S_DIM];
    if (j < S_DIM) mi[j] = mask[j * N_DIM + i];
    __syncthreads();
    float acc = 0.f;
    #pragma unroll 8
    for (int s = 0; s < S_DIM; s++) acc += mi[s] * mask[s * N_DIM + j];
    g_norm[i * N_DIM + j] = acc + OPM_EPS;
}

__global__ void woT_kernel(const float* __restrict__ wo) {
    int idx = blockIdx.x * 256 + threadIdx.x;   // 131072
    int z = idx >> 10, k = idx & 1023;
    g_woT[idx] = __uint_as_float(rna_tf32(wo[k * CZ + z]));
}

// ============================================================================
// GEMM1: O[8192,8192] = A[8192,128]*B[8192,128]^T.  128x128 CTA, 8 warps
// (2M x 4N) of 64x32, cp.async 3-stage pipeline, NC=4 chunks, 2 CTAs/SM.
// ============================================================================
__global__ void __launch_bounds__(256, 2) gemm1_mma() {
    extern __shared__ __align__(16) float sm[];
    const uint32_t sbase = smem_u32(sm);
    const int tid = threadIdx.x, wid = tid >> 5, lane = tid & 31;
    const int wm = (wid & 1) * 64, wn = (wid >> 1) * 32;
    const int p0 = blockIdx.y * 128, q0 = blockIdx.x * 128;
    const int lg = lane >> 3, lrow = lane & 7;
    const uint32_t a_lo = (uint32_t)(wm + (lg & 1) * 8 + lrow) * ROW_BYTES
                        + (uint32_t)(lg >> 1) * 16;
    const uint32_t b_lo = B_OFF + (uint32_t)(wn + (lg >> 1) * 8 + lrow) * ROW_BYTES
                        + (uint32_t)(lg & 1) * 16;

    float acc[4][4][4];
    #pragma unroll
    for (int a = 0; a < 4; a++)
        #pragma unroll
        for (int b = 0; b < 4; b++)
            #pragma unroll
            for (int e = 0; e < 4; e++) acc[a][b][e] = 0.f;

    auto copy1 = [&](int ch, int st) {
        const int kb = ch * 32;
        const uint32_t dA = sbase + st * STAGE_BYTES;
        const uint32_t dB = dA + B_OFF;
        #pragma unroll
        for (int i = 0; i < 4; i++) {
            int f = tid + i * 256, rr = f >> 3, cc = f & 7;
            cp16(dA + rr * ROW_BYTES + cc * 16,
                 &g_a[(size_t)(p0 + rr) * S_DIM + kb + cc * 4]);
            cp16(dB + rr * ROW_BYTES + cc * 16,
                 &g_b[(size_t)(q0 + rr) * S_DIM + kb + cc * 4]);
        }
    };

    copy1(0, 0); CP_COMMIT();
    copy1(1, 1); CP_COMMIT();

    #pragma unroll
    for (int ch = 0; ch < 4; ch++) {
        CP_WAIT1();
        __syncthreads();
        const uint32_t so = sbase + (uint32_t)(ch % 3) * STAGE_BYTES;
        mma_chunk(so + a_lo, so + b_lo, acc);
        if (ch + 2 < 4) copy1(ch + 2, (ch + 2) % 3);
        CP_COMMIT();
    }

    // epilogue -> g_O (tf32-rounded)
    #pragma unroll
    for (int mt = 0; mt < 4; mt++) {
        const int row0 = p0 + wm + mt * 16 + (lane >> 2);
        #pragma unroll
        for (int nt = 0; nt < 4; nt++) {
            const int col = q0 + wn + nt * 8 + (lane & 3) * 2;
            float2 v0, v1;
            v0.x = __uint_as_float(rna_tf32(acc[mt][nt][0]));
            v0.y = __uint_as_float(rna_tf32(acc[mt][nt][1]));
            v1.x = __uint_as_float(rna_tf32(acc[mt][nt][2]));
            v1.y = __uint_as_float(rna_tf32(acc[mt][nt][3]));
            *(float2*)&g_O[(size_t)row0 * P_DIM + col]       = v0;
            *(float2*)&g_O[(size_t)(row0 + 8) * P_DIM + col] = v1;
        }
    }
}

// ============================================================================
// GEMM2: out[65536,128] = O'[65536,1024] @ woT^T (+bo, /norm).
// 128x128 CTA, 8 warps (2M x 4N) of 64x32, cp.async 3-stage, NC=32 chunks.
// ============================================================================
__global__ void __launch_bounds__(256, 2) gemm2_mma(const float* __restrict__ bo,
                                                    float* __restrict__ out) {
    extern __shared__ __align__(16) float sm[];
    const uint32_t sbase = smem_u32(sm);
    const int tid = threadIdx.x, wid = tid >> 5, lane = tid & 31;
    const int wm = (wid & 1) * 64, wn = (wid >> 1) * 32;
    const int m0 = blockIdx.x * 128;
    const int i_idx = m0 >> 8, j0 = m0 & 255;
    const int lg = lane >> 3, lrow = lane & 7;
    const uint32_t a_lo = (uint32_t)(wm + (lg & 1) * 8 + lrow) * ROW_BYTES
                        + (uint32_t)(lg >> 1) * 16;
    const uint32_t b_lo = B_OFF + (uint32_t)(wn + (lg >> 1) * 8 + lrow) * ROW_BYTES
                        + (uint32_t)(lg & 1) * 16;

    float acc[4][4][4];
    #pragma unroll
    for (int a = 0; a < 4; a++)
        #pragma unroll
        for (int b = 0; b < 4; b++)
            #pragma unroll
            for (int e = 0; e < 4; e++) acc[a][b][e] = 0.f;

    auto copy1 = [&](int ch, int st) {
        const float* gA = &g_O[((size_t)(i_idx * 32 + ch)) * P_DIM + (size_t)j0 * 32];
        const uint32_t dA = sbase + st * STAGE_BYTES;
        const uint32_t dB = dA + B_OFF;
        #pragma unroll
        for (int i = 0; i < 4; i++) {
            int f = tid + i * 256, rr = f >> 3, cc = f & 7;
            cp16(dA + rr * ROW_BYTES + cc * 16, &gA[f * 4]);
            cp16(dB + rr * ROW_BYTES + cc * 16,
                 &g_woT[(size_t)rr * 1024 + ch * 32 + cc * 4]);
        }
    };

    copy1(0, 0); CP_COMMIT();
    copy1(1, 1); CP_COMMIT();

    int st = 0;
    for (int ch = 0; ch < 32; ch++) {
        CP_WAIT1();
        __syncthreads();
        const uint32_t so = sbase + (uint32_t)st * STAGE_BYTES;
        mma_chunk(so + a_lo, so + b_lo, acc);
        if (ch + 2 < 32) {
            int ns = st + 2; if (ns >= 3) ns -= 3;
            copy1(ch + 2, ns);
        }
        CP_COMMIT();
        if (++st == 3) st = 0;
    }

    // epilogue: +bo, /norm
    #pragma unroll
    for (int mt = 0; mt < 4; mt++) {
        const int row0 = m0 + wm + mt * 16 + (lane >> 2);
        const float inv0 = 1.0f / g_norm[row0];
        const float inv1 = 1.0f / g_norm[row0 + 8];
        #pragma unroll
        for (int nt = 0; nt < 4; nt++) {
            const int col = wn + nt * 8 + (lane & 3) * 2;
            const float b0v = bo[col], b1v = bo[col + 1];
            float2 v0, v1;
            v0.x = (acc[mt][nt][0] + b0v) * inv0;
            v0.y = (acc[mt][nt][1] + b1v) * inv0;
            v1.x = (acc[mt][nt][2] + b0v) * inv1;
            v1.y = (acc[mt][nt][3] + b1v) * inv1;
            *(float2*)&out[(size_t)row0 * CZ + col]       = v0;
            *(float2*)&out[(size_t)(row0 + 8) * CZ + col] = v1;
        }
    }
}

// ============================================================================
extern "C" void kernel_launch(void* const* d_in, const int* in_sizes, int n_in,
                              void* d_out, int out_size) {
    const float* m    = (const float*)d_in[0];
    const float* mask = (const float*)d_in[1];
    const float* ln_w = (const float*)d_in[2];
    const float* ln_b = (const float*)d_in[3];
    const float* w1   = (const float*)d_in[4];
    const float* b1   = (const float*)d_in[5];
    const float* w2   = (const float*)d_in[6];
    const float* b2   = (const float*)d_in[7];
    const float* wo   = (const float*)d_in[8];
    const float* bo   = (const float*)d_in[9];
    float* out = (float*)d_out;

    cudaFuncSetAttribute(ln_proj_kernel, cudaFuncAttributeMaxDynamicSharedMemorySize, 67584);
    cudaFuncSetAttribute(gemm1_mma, cudaFuncAttributeMaxDynamicSharedMemorySize, SMEM_BYTES);
    cudaFuncSetAttribute(gemm2_mma, cudaFuncAttributeMaxDynamicSharedMemorySize, SMEM_BYTES);

    ln_proj_kernel<<<2048, 256, 67584>>>(m, mask, ln_w, ln_b, w1, b1, w2, b2);
    norm_kernel<<<N_DIM, 256>>>(mask);
    woT_kernel<<<512, 256>>>(wo);

    dim3 g1(64, 64);
    gemm1_mma<<<g1, 256, SMEM_BYTES>>>();
    gemm2_mma<<<512, 256, SMEM_BYTES>>>(bo, out);
}

// round 10
// speedup vs baseline: 1.6388x; 1.5436x over previous
#include <cuda_runtime.h>
#include <cstdint>

#define S_DIM 128
#define N_DIM 256
#define CM 256
#define CH 32
#define CZ 128
#define P_DIM 8192
#define LN_EPS 1e-5f
#define OPM_EPS 1e-3f

__device__ __align__(16) float g_a[P_DIM * S_DIM];          // [p=(n,h)][s] tf32-rounded
__device__ __align__(16) float g_b[P_DIM * S_DIM];          // [q=(n,h)][s] tf32-rounded
__device__ __align__(16) float g_O[(size_t)P_DIM * P_DIM];  // [(i,c)][(j,d)] tf32-rounded
__device__ __align__(16) float g_woT[CZ * CH * CH];         // [z][k=(c,d)] tf32-rounded
__device__ __align__(16) float g_wpT[64 * CM];              // [h][k] = lnw[k]*W[k,h], tf32
__device__ float g_cw[64];                                  // colsum of rounded W'
__device__ float g_c2[64];                                  // lnb@W + bias
__device__ __align__(8) float2 g_stat2[N_DIM * S_DIM];      // [n*128+s] = (r, mu*r)
__device__ float g_norm[N_DIM * N_DIM];

__device__ __forceinline__ uint32_t rna_tf32(float x) {
    uint32_t r;
    asm("cvt.rna.tf32.f32 %0, %1;" : "=r"(r) : "f"(x));
    return r;
}
__device__ __forceinline__ uint32_t smem_u32(const void* p) {
    uint32_t a;
    asm("{ .reg .u64 t; cvta.to.shared.u64 t, %1; cvt.u32.u64 %0, t; }" : "=r"(a) : "l"(p));
    return a;
}
__device__ __forceinline__ void mma_tf32(float* c, const uint32_t* a, const uint32_t* b) {
    asm volatile(
        "mma.sync.aligned.m16n8k8.row.col.f32.tf32.tf32.f32 "
        "{%0,%1,%2,%3}, {%4,%5,%6,%7}, {%8,%9}, {%0,%1,%2,%3};\n"
        : "+f"(c[0]), "+f"(c[1]), "+f"(c[2]), "+f"(c[3])
        : "r"(a[0]), "r"(a[1]), "r"(a[2]), "r"(a[3]), "r"(b[0]), "r"(b[1]));
}
__device__ __forceinline__ void ldsm_x4(uint32_t* r, uint32_t addr) {
    asm volatile("ldmatrix.sync.aligned.m8n8.x4.shared.b16 {%0,%1,%2,%3}, [%4];"
        : "=r"(r[0]), "=r"(r[1]), "=r"(r[2]), "=r"(r[3]) : "r"(addr));
}
__device__ __forceinline__ void cp16(uint32_t d, const float* s) {
    asm volatile("cp.async.cg.shared.global [%0], [%1], 16;" :: "r"(d), "l"(s));
}
__device__ __forceinline__ void cp16_ca(uint32_t d, const float* s) {
    asm volatile("cp.async.ca.shared.global [%0], [%1], 16;" :: "r"(d), "l"(s));
}
#define CP_COMMIT() asm volatile("cp.async.commit_group;" ::: "memory")
#define CP_WAIT1()  asm volatile("cp.async.wait_group 1;" ::: "memory")

// GEMM1/2 stage layout: [A 128x36 | B 128x36] per stage, 3 stages.
#define ROW_BYTES   144u
#define STAGE_BYTES 36864u
#define B_OFF       18432u
#define SMEM_BYTES  (3 * 36864)
// proj stage layout: [A 128x36 | B 64x36], 3 stages.
#define PSTAGE_BYTES 27648u
#define PB_OFF       18432u
#define PSMEM_BYTES  (3 * 27648)

// 64x32 warp tile, one 32-K chunk: 6 ldmatrix.x4 feed 16 MMAs per kk-step.
__device__ __forceinline__ void mma_chunk(uint32_t a_base, uint32_t b_base,
                                          float acc[4][4][4]) {
    #pragma unroll
    for (int kk = 0; kk < 4; kk++) {
        uint32_t af[4][4], bf[4][2];
        #pragma unroll
        for (int mt = 0; mt < 4; mt++)
            ldsm_x4(af[mt], a_base + kk * 32 + mt * (16 * ROW_BYTES));
        #pragma unroll
        for (int pr = 0; pr < 2; pr++) {
            uint32_t t[4];
            ldsm_x4(t, b_base + kk * 32 + pr * (16 * ROW_BYTES));
            bf[2 * pr][0] = t[0]; bf[2 * pr][1] = t[1];
            bf[2 * pr + 1][0] = t[2]; bf[2 * pr + 1][1] = t[3];
        }
        #pragma unroll
        for (int mt = 0; mt < 4; mt++)
            #pragma unroll
            for (int nt = 0; nt < 4; nt++)
                mma_tf32(acc[mt][nt], af[mt], bf[nt]);
    }
}

// ============================================================================
// stats: per row (s,n): r = rsqrt(var+eps), mur = mu*r -> g_stat2[n*128+s]
// ============================================================================
__global__ void __launch_bounds__(256) stats_kernel(const float* __restrict__ m) {
    const int row = blockIdx.x * 8 + (threadIdx.x >> 5);
    const int lane = threadIdx.x & 31;
    const float* src = m + (size_t)row * CM;
    float4 v0 = *(const float4*)&src[lane * 4];
    float4 v1 = *(const float4*)&src[128 + lane * 4];
    float s1 = v0.x + v0.y + v0.z + v0.w + v1.x + v1.y + v1.z + v1.w;
    float s2 = v0.x*v0.x + v0.y*v0.y + v0.z*v0.z + v0.w*v0.w
             + v1.x*v1.x + v1.y*v1.y + v1.z*v1.z + v1.w*v1.w;
    #pragma unroll
    for (int o = 16; o > 0; o >>= 1) {
        s1 += __shfl_xor_sync(0xffffffff, s1, o);
        s2 += __shfl_xor_sync(0xffffffff, s2, o);
    }
    if (lane == 0) {
        float mu = s1 * (1.f / CM);
        float var = s2 * (1.f / CM) - mu * mu;
        float r = rsqrtf(var + LN_EPS);
        const int s = row >> 8, n = row & 255;
        g_stat2[n * S_DIM + s] = make_float2(r, mu * r);
    }
}

// ============================================================================
// prep: wpT[h][k] = rna(lnw[k]*W[k,h]); cw[h]=colsum(rounded); c2 = lnb@W + bias
// ============================================================================
__global__ void __launch_bounds__(256) prep_kernel(
        const float* __restrict__ w1, const float* __restrict__ b1,
        const float* __restrict__ w2, const float* __restrict__ b2,
        const float* __restrict__ ln_w, const float* __restrict__ ln_b) {
    const int h = threadIdx.x & 63, kq = threadIdx.x >> 6;
    const float* w = (h < 32) ? w1 : w2;
    const int hh = h & 31;
    float cw = 0.f, cb = 0.f;
    for (int k = kq * 64; k < kq * 64 + 64; k++) {
        float v = ln_w[k] * w[k * CH + hh];
        float rv = __uint_as_float(rna_tf32(v));
        g_wpT[h * CM + k] = rv;
        cw += rv;
        cb += ln_b[k] * w[k * CH + hh];
    }
    __shared__ float scw[4][64], scb[4][64];
    scw[kq][h] = cw; scb[kq][h] = cb;
    __syncthreads();
    if (kq == 0) {
        g_cw[h] = scw[0][h] + scw[1][h] + scw[2][h] + scw[3][h];
        float tb = scb[0][h] + scb[1][h] + scb[2][h] + scb[3][h];
        g_c2[h] = tb + ((h < 32) ? b1[h] : b2[hh]);
    }
}

// ============================================================================
// proj_mma: X[32768x256] @ W'[256x64] via mma, n-major row order.
// CTA tile 128(M=one n, all s) x 64(N=h), 4 warps 2x2 of 64x32, K=8 chunks.
// Epilogue: val = (r*dot - mur*cw[h] + c2[h]) * mask, rna -> g_a/g_b.
// ============================================================================
__global__ void __launch_bounds__(128) proj_mma(const float* __restrict__ m,
                                                const float* __restrict__ mask) {
    extern __shared__ __align__(16) float sm[];
    const uint32_t sbase = smem_u32(sm);
    const int tid = threadIdx.x, wid = tid >> 5, lane = tid & 31;
    const int wm = (wid & 1) * 64, wn = (wid >> 1) * 32;
    const int n = blockIdx.x;                 // fixed n per CTA; rows = s 0..127
    const int lg = lane >> 3, lrow = lane & 7;
    const uint32_t a_lo = (uint32_t)(wm + (lg & 1) * 8 + lrow) * ROW_BYTES
                        + (uint32_t)(lg >> 1) * 16;
    const uint32_t b_lo = PB_OFF + (uint32_t)(wn + (lg >> 1) * 8 + lrow) * ROW_BYTES
                        + (uint32_t)(lg & 1) * 16;

    float acc[4][4][4];
    #pragma unroll
    for (int a = 0; a < 4; a++)
        #pragma unroll
        for (int b = 0; b < 4; b++)
            #pragma unroll
            for (int e = 0; e < 4; e++) acc[a][b][e] = 0.f;

    auto copy1 = [&](int ch, int st) {
        const int kb = ch * 32;
        const uint32_t dA = sbase + st * PSTAGE_BYTES;
        const uint32_t dB = dA + PB_OFF;
        #pragma unroll
        for (int i = 0; i < 8; i++) {         // A: 128 s-rows x 32 k
            int f = tid + i * 128, rr = f >> 3, cc = f & 7;
            cp16(dA + rr * ROW_BYTES + cc * 16,
                 &m[((size_t)rr * N_DIM + n) * CM + kb + cc * 4]);
        }
        #pragma unroll
        for (int i = 0; i < 4; i++) {         // B: 64 h-rows x 32 k
            int f = tid + i * 128, rr = f >> 3, cc = f & 7;
            cp16_ca(dB + rr * ROW_BYTES + cc * 16,
                    &g_wpT[rr * CM + kb + cc * 4]);
        }
    };

    copy1(0, 0); CP_COMMIT();
    copy1(1, 1); CP_COMMIT();

    int st = 0;
    #pragma unroll 1
    for (int ch = 0; ch < 8; ch++) {
        CP_WAIT1();
        __syncthreads();
        const uint32_t so = sbase + (uint32_t)st * PSTAGE_BYTES;
        mma_chunk(so + a_lo, so + b_lo, acc);
        if (ch + 2 < 8) {
            int ns = st + 2; if (ns >= 3) ns -= 3;
            copy1(ch + 2, ns);
        }
        CP_COMMIT();
        if (++st == 3) st = 0;
    }

    // epilogue: per-row stats, per-col constants, mask, rna, scatter
    float* dst = (wn == 0) ? g_a : g_b;
    #pragma unroll
    for (int mt = 0; mt < 4; mt++) {
        const int s0 = wm + mt * 16 + (lane >> 2);
        const float2 st0 = g_stat2[n * S_DIM + s0];
        const float2 st1 = g_stat2[n * S_DIM + s0 + 8];
        const float mk0 = mask[s0 * N_DIM + n];
        const float mk1 = mask[(s0 + 8) * N_DIM + n];
        #pragma unroll
        for (int nt = 0; nt < 4; nt++) {
            const int h = wn + nt * 8 + (lane & 3) * 2;
            const int hh = h & 31;
            const float cwa = g_cw[h], cwb = g_cw[h + 1];
            const float c2a = g_c2[h], c2b = g_c2[h + 1];
            float* d0 = &dst[(size_t)(n * CH + hh) * S_DIM];
            float* d1 = d0 + S_DIM;
            d0[s0]     = __uint_as_float(rna_tf32((st0.x * acc[mt][nt][0] - st0.y * cwa + c2a) * mk0));
            d1[s0]     = __uint_as_float(rna_tf32((st0.x * acc[mt][nt][1] - st0.y * cwb + c2b) * mk0));
            d0[s0 + 8] = __uint_as_float(rna_tf32((st1.x * acc[mt][nt][2] - st1.y * cwa + c2a) * mk1));
            d1[s0 + 8] = __uint_as_float(rna_tf32((st1.x * acc[mt][nt][3] - st1.y * cwb + c2b) * mk1));
        }
    }
}

// ============================================================================
// norm + woT
// ============================================================================
__global__ void norm_kernel(const float* __restrict__ mask) {
    const int i = blockIdx.x, j = threadIdx.x;
    __shared__ float mi[S_DIM];
    if (j < S_DIM) mi[j] = mask[j * N_DIM + i];
    __syncthreads();
    float acc = 0.f;
    #pragma unroll 8
    for (int s = 0; s < S_DIM; s++) acc += mi[s] * mask[s * N_DIM + j];
    g_norm[i * N_DIM + j] = acc + OPM_EPS;
}

__global__ void woT_kernel(const float* __restrict__ wo) {
    int idx = blockIdx.x * 256 + threadIdx.x;   // 131072
    int z = idx >> 10, k = idx & 1023;
    g_woT[idx] = __uint_as_float(rna_tf32(wo[k * CZ + z]));
}

// ============================================================================
// GEMM1: O[8192,8192] = A[8192,128]*B[8192,128]^T.  128x128 CTA, 8 warps
// (2M x 4N) of 64x32, cp.async 3-stage pipeline, NC=4 chunks, 2 CTAs/SM.
// ============================================================================
__global__ void __launch_bounds__(256, 2) gemm1_mma() {
    extern __shared__ __align__(16) float sm[];
    const uint32_t sbase = smem_u32(sm);
    const int tid = threadIdx.x, wid = tid >> 5, lane = tid & 31;
    const int wm = (wid & 1) * 64, wn = (wid >> 1) * 32;
    const int p0 = blockIdx.y * 128, q0 = blockIdx.x * 128;
    const int lg = lane >> 3, lrow = lane & 7;
    const uint32_t a_lo = (uint32_t)(wm + (lg & 1) * 8 + lrow) * ROW_BYTES
                        + (uint32_t)(lg >> 1) * 16;
    const uint32_t b_lo = B_OFF + (uint32_t)(wn + (lg >> 1) * 8 + lrow) * ROW_BYTES
                        + (uint32_t)(lg & 1) * 16;

    float acc[4][4][4];
    #pragma unroll
    for (int a = 0; a < 4; a++)
        #pragma unroll
        for (int b = 0; b < 4; b++)
            #pragma unroll
            for (int e = 0; e < 4; e++) acc[a][b][e] = 0.f;

    auto copy1 = [&](int ch, int st) {
        const int kb = ch * 32;
        const uint32_t dA = sbase + st * STAGE_BYTES;
        const uint32_t dB = dA + B_OFF;
        #pragma unroll
        for (int i = 0; i < 4; i++) {
            int f = tid + i * 256, rr = f >> 3, cc = f & 7;
            cp16(dA + rr * ROW_BYTES + cc * 16,
                 &g_a[(size_t)(p0 + rr) * S_DIM + kb + cc * 4]);
            cp16(dB + rr * ROW_BYTES + cc * 16,
                 &g_b[(size_t)(q0 + rr) * S_DIM + kb + cc * 4]);
        }
    };

    copy1(0, 0); CP_COMMIT();
    copy1(1, 1); CP_COMMIT();

    #pragma unroll
    for (int ch = 0; ch < 4; ch++) {
        CP_WAIT1();
        __syncthreads();
        const uint32_t so = sbase + (uint32_t)(ch % 3) * STAGE_BYTES;
        mma_chunk(so + a_lo, so + b_lo, acc);
        if (ch + 2 < 4) copy1(ch + 2, (ch + 2) % 3);
        CP_COMMIT();
    }

    // epilogue -> g_O (tf32-rounded)
    #pragma unroll
    for (int mt = 0; mt < 4; mt++) {
        const int row0 = p0 + wm + mt * 16 + (lane >> 2);
        #pragma unroll
        for (int nt = 0; nt < 4; nt++) {
            const int col = q0 + wn + nt * 8 + (lane & 3) * 2;
            float2 v0, v1;
            v0.x = __uint_as_float(rna_tf32(acc[mt][nt][0]));
            v0.y = __uint_as_float(rna_tf32(acc[mt][nt][1]));
            v1.x = __uint_as_float(rna_tf32(acc[mt][nt][2]));
            v1.y = __uint_as_float(rna_tf32(acc[mt][nt][3]));
            *(float2*)&g_O[(size_t)row0 * P_DIM + col]       = v0;
            *(float2*)&g_O[(size_t)(row0 + 8) * P_DIM + col] = v1;
        }
    }
}

// ============================================================================
// GEMM2: out[65536,128] = O'[65536,1024] @ woT^T (+bo, /norm).
// 128x128 CTA, 8 warps (2M x 4N) of 64x32, cp.async 3-stage, NC=32 chunks.
// ============================================================================
__global__ void __launch_bounds__(256, 2) gemm2_mma(const float* __restrict__ bo,
                                                    float* __restrict__ out) {
    extern __shared__ __align__(16) float sm[];
    const uint32_t sbase = smem_u32(sm);
    const int tid = threadIdx.x, wid = tid >> 5, lane = tid & 31;
    const int wm = (wid & 1) * 64, wn = (wid >> 1) * 32;
    const int m0 = blockIdx.x * 128;
    const int i_idx = m0 >> 8, j0 = m0 & 255;
    const int lg = lane >> 3, lrow = lane & 7;
    const uint32_t a_lo = (uint32_t)(wm + (lg & 1) * 8 + lrow) * ROW_BYTES
                        + (uint32_t)(lg >> 1) * 16;
    const uint32_t b_lo = B_OFF + (uint32_t)(wn + (lg >> 1) * 8 + lrow) * ROW_BYTES
                        + (uint32_t)(lg & 1) * 16;

    float acc[4][4][4];
    #pragma unroll
    for (int a = 0; a < 4; a++)
        #pragma unroll
        for (int b = 0; b < 4; b++)
            #pragma unroll
            for (int e = 0; e < 4; e++) acc[a][b][e] = 0.f;

    auto copy1 = [&](int ch, int st) {
        const float* gA = &g_O[((size_t)(i_idx * 32 + ch)) * P_DIM + (size_t)j0 * 32];
        const uint32_t dA = sbase + st * STAGE_BYTES;
        const uint32_t dB = dA + B_OFF;
        #pragma unroll
        for (int i = 0; i < 4; i++) {
            int f = tid + i * 256, rr = f >> 3, cc = f & 7;
            cp16(dA + rr * ROW_BYTES + cc * 16, &gA[f * 4]);
            cp16_ca(dB + rr * ROW_BYTES + cc * 16,
                    &g_woT[(size_t)rr * 1024 + ch * 32 + cc * 4]);
        }
    };

    copy1(0, 0); CP_COMMIT();
    copy1(1, 1); CP_COMMIT();

    int st = 0;
    for (int ch = 0; ch < 32; ch++) {
        CP_WAIT1();
        __syncthreads();
        const uint32_t so = sbase + (uint32_t)st * STAGE_BYTES;
        mma_chunk(so + a_lo, so + b_lo, acc);
        if (ch + 2 < 32) {
            int ns = st + 2; if (ns >= 3) ns -= 3;
            copy1(ch + 2, ns);
        }
        CP_COMMIT();
        if (++st == 3) st = 0;
    }

    // epilogue: +bo, /norm
    #pragma unroll
    for (int mt = 0; mt < 4; mt++) {
        const int row0 = m0 + wm + mt * 16 + (lane >> 2);
        const float inv0 = 1.0f / g_norm[row0];
        const float inv1 = 1.0f / g_norm[row0 + 8];
        #pragma unroll
        for (int nt = 0; nt < 4; nt++) {
            const int col = wn + nt * 8 + (lane & 3) * 2;
            const float b0v = bo[col], b1v = bo[col + 1];
            float2 v0, v1;
            v0.x = (acc[mt][nt][0] + b0v) * inv0;
            v0.y = (acc[mt][nt][1] + b1v) * inv0;
            v1.x = (acc[mt][nt][2] + b0v) * inv1;
            v1.y = (acc[mt][nt][3] + b1v) * inv1;
            *(float2*)&out[(size_t)row0 * CZ + col]       = v0;
            *(float2*)&out[(size_t)(row0 + 8) * CZ + col] = v1;
        }
    }
}

// ============================================================================
extern "C" void kernel_launch(void* const* d_in, const int* in_sizes, int n_in,
                              void* d_out, int out_size) {
    const float* m    = (const float*)d_in[0];
    const float* mask = (const float*)d_in[1];
    const float* ln_w = (const float*)d_in[2];
    const float* ln_b = (const float*)d_in[3];
    const float* w1   = (const float*)d_in[4];
    const float* b1   = (const float*)d_in[5];
    const float* w2   = (const float*)d_in[6];
    const float* b2   = (const float*)d_in[7];
    const float* wo   = (const float*)d_in[8];
    const float* bo   = (const float*)d_in[9];
    float* out = (float*)d_out;

    cudaFuncSetAttribute(proj_mma, cudaFuncAttributeMaxDynamicSharedMemorySize, PSMEM_BYTES);
    cudaFuncSetAttribute(gemm1_mma, cudaFuncAttributeMaxDynamicSharedMemorySize, SMEM_BYTES);
    cudaFuncSetAttribute(gemm2_mma, cudaFuncAttributeMaxDynamicSharedMemorySize, SMEM_BYTES);

    stats_kernel<<<4096, 256>>>(m);
    prep_kernel<<<1, 256>>>(w1, b1, w2, b2, ln_w, ln_b);
    norm_kernel<<<N_DIM, 256>>>(mask);
    woT_kernel<<<512, 256>>>(wo);

    proj_mma<<<256, 128, PSMEM_BYTES>>>(m, mask);

    dim3 g1(64, 64);
    gemm1_mma<<<g1, 256, SMEM_BYTES>>>();
    gemm2_mma<<<512, 256, SMEM_BYTES>>>(bo, out);
}

// round 11
// speedup vs baseline: 1.6390x; 1.0001x over previous
#include <cuda_runtime.h>
#include <cstdint>

#define S_DIM 128
#define N_DIM 256
#define CM 256
#define CH 32
#define CZ 128
#define P_DIM 8192
#define LN_EPS 1e-5f
#define OPM_EPS 1e-3f

__device__ __align__(16) float g_a[P_DIM * S_DIM];          // [p=(n,h)][s] tf32-rounded
__device__ __align__(16) float g_b[P_DIM * S_DIM];          // [q=(n,h)][s] tf32-rounded
__device__ __align__(16) float g_O[(size_t)P_DIM * P_DIM];  // [(i,c)][(j,d)] tf32-rounded
__device__ __align__(16) float g_woT[CZ * CH * CH];         // [z][k=(c,d)] tf32-rounded
__device__ __align__(16) float g_wpT[64 * CM];              // [h][k] = lnw[k]*W[k,h], tf32
__device__ __align__(16) float g_mr[(size_t)N_DIM * S_DIM * CM]; // rna(m), n-major
__device__ float g_cw[64];                                  // colsum of rounded W'
__device__ float g_c2[64];                                  // lnb@W + bias
__device__ __align__(8) float2 g_stat2[N_DIM * S_DIM];      // [n*128+s] = (r, mu*r)
__device__ float g_norm[N_DIM * N_DIM];

__device__ __forceinline__ uint32_t rna_tf32(float x) {
    uint32_t r;
    asm("cvt.rna.tf32.f32 %0, %1;" : "=r"(r) : "f"(x));
    return r;
}
__device__ __forceinline__ uint32_t smem_u32(const void* p) {
    uint32_t a;
    asm("{ .reg .u64 t; cvta.to.shared.u64 t, %1; cvt.u32.u64 %0, t; }" : "=r"(a) : "l"(p));
    return a;
}
__device__ __forceinline__ void mma_tf32(float* c, const uint32_t* a, const uint32_t* b) {
    asm volatile(
        "mma.sync.aligned.m16n8k8.row.col.f32.tf32.tf32.f32 "
        "{%0,%1,%2,%3}, {%4,%5,%6,%7}, {%8,%9}, {%0,%1,%2,%3};\n"
        : "+f"(c[0]), "+f"(c[1]), "+f"(c[2]), "+f"(c[3])
        : "r"(a[0]), "r"(a[1]), "r"(a[2]), "r"(a[3]), "r"(b[0]), "r"(b[1]));
}
__device__ __forceinline__ void ldsm_x4(uint32_t* r, uint32_t addr) {
    asm volatile("ldmatrix.sync.aligned.m8n8.x4.shared.b16 {%0,%1,%2,%3}, [%4];"
        : "=r"(r[0]), "=r"(r[1]), "=r"(r[2]), "=r"(r[3]) : "r"(addr));
}
__device__ __forceinline__ void cp16(uint32_t d, const float* s) {
    asm volatile("cp.async.cg.shared.global [%0], [%1], 16;" :: "r"(d), "l"(s));
}
__device__ __forceinline__ void cp16_ca(uint32_t d, const float* s) {
    asm volatile("cp.async.ca.shared.global [%0], [%1], 16;" :: "r"(d), "l"(s));
}
#define CP_COMMIT() asm volatile("cp.async.commit_group;" ::: "memory")
#define CP_WAIT1()  asm volatile("cp.async.wait_group 1;" ::: "memory")

// GEMM1/2 stage layout: [A 128x36 | B 128x36] per stage, 3 stages.
#define ROW_BYTES   144u
#define STAGE_BYTES 36864u
#define B_OFF       18432u
#define SMEM_BYTES  (3 * 36864)
// proj stage layout: [A 128x36 | B 64x36], 3 stages.
#define PSTAGE_BYTES 27648u
#define PB_OFF       18432u
#define PSMEM_BYTES  (3 * 27648)

// 64x32 warp tile, one 32-K chunk: 6 ldmatrix.x4 feed 16 MMAs per kk-step.
__device__ __forceinline__ void mma_chunk(uint32_t a_base, uint32_t b_base,
                                          float acc[4][4][4]) {
    #pragma unroll
    for (int kk = 0; kk < 4; kk++) {
        uint32_t af[4][4], bf[4][2];
        #pragma unroll
        for (int mt = 0; mt < 4; mt++)
            ldsm_x4(af[mt], a_base + kk * 32 + mt * (16 * ROW_BYTES));
        #pragma unroll
        for (int pr = 0; pr < 2; pr++) {
            uint32_t t[4];
            ldsm_x4(t, b_base + kk * 32 + pr * (16 * ROW_BYTES));
            bf[2 * pr][0] = t[0]; bf[2 * pr][1] = t[1];
            bf[2 * pr + 1][0] = t[2]; bf[2 * pr + 1][1] = t[3];
        }
        #pragma unroll
        for (int mt = 0; mt < 4; mt++)
            #pragma unroll
            for (int nt = 0; nt < 4; nt++)
                mma_tf32(acc[mt][nt], af[mt], bf[nt]);
    }
}

// ============================================================================
// stats: per row (s,n): r = rsqrt(var+eps), mur = mu*r -> g_stat2[n*128+s];
// also writes rna-rounded m into g_mr in n-major order (coalesced for proj).
// ============================================================================
__global__ void __launch_bounds__(256) stats_kernel(const float* __restrict__ m) {
    const int row = blockIdx.x * 8 + (threadIdx.x >> 5);
    const int lane = threadIdx.x & 31;
    const float* src = m + (size_t)row * CM;
    float4 v0 = *(const float4*)&src[lane * 4];
    float4 v1 = *(const float4*)&src[128 + lane * 4];
    float s1 = v0.x + v0.y + v0.z + v0.w + v1.x + v1.y + v1.z + v1.w;
    float s2 = v0.x*v0.x + v0.y*v0.y + v0.z*v0.z + v0.w*v0.w
             + v1.x*v1.x + v1.y*v1.y + v1.z*v1.z + v1.w*v1.w;
    #pragma unroll
    for (int o = 16; o > 0; o >>= 1) {
        s1 += __shfl_xor_sync(0xffffffff, s1, o);
        s2 += __shfl_xor_sync(0xffffffff, s2, o);
    }
    const int s = row >> 8, n = row & 255;
    // rounded n-major copy for proj_mma's A operand (unbiased tf32)
    float* dst = &g_mr[((size_t)n * S_DIM + s) * CM];
    float4 r0, r1;
    r0.x = __uint_as_float(rna_tf32(v0.x)); r0.y = __uint_as_float(rna_tf32(v0.y));
    r0.z = __uint_as_float(rna_tf32(v0.z)); r0.w = __uint_as_float(rna_tf32(v0.w));
    r1.x = __uint_as_float(rna_tf32(v1.x)); r1.y = __uint_as_float(rna_tf32(v1.y));
    r1.z = __uint_as_float(rna_tf32(v1.z)); r1.w = __uint_as_float(rna_tf32(v1.w));
    *(float4*)&dst[lane * 4]       = r0;
    *(float4*)&dst[128 + lane * 4] = r1;
    if (lane == 0) {
        float mu = s1 * (1.f / CM);
        float var = s2 * (1.f / CM) - mu * mu;
        float r = rsqrtf(var + LN_EPS);
        g_stat2[n * S_DIM + s] = make_float2(r, mu * r);
    }
}

// ============================================================================
// prep: wpT[h][k] = rna(lnw[k]*W[k,h]); cw[h]=colsum(rounded); c2 = lnb@W + bias
// ============================================================================
__global__ void __launch_bounds__(256) prep_kernel(
        const float* __restrict__ w1, const float* __restrict__ b1,
        const float* __restrict__ w2, const float* __restrict__ b2,
        const float* __restrict__ ln_w, const float* __restrict__ ln_b) {
    const int h = threadIdx.x & 63, kq = threadIdx.x >> 6;
    const float* w = (h < 32) ? w1 : w2;
    const int hh = h & 31;
    float cw = 0.f, cb = 0.f;
    for (int k = kq * 64; k < kq * 64 + 64; k++) {
        float v = ln_w[k] * w[k * CH + hh];
        float rv = __uint_as_float(rna_tf32(v));
        g_wpT[h * CM + k] = rv;
        cw += rv;
        cb += ln_b[k] * w[k * CH + hh];
    }
    __shared__ float scw[4][64], scb[4][64];
    scw[kq][h] = cw; scb[kq][h] = cb;
    __syncthreads();
    if (kq == 0) {
        g_cw[h] = scw[0][h] + scw[1][h] + scw[2][h] + scw[3][h];
        float tb = scb[0][h] + scb[1][h] + scb[2][h] + scb[3][h];
        g_c2[h] = tb + ((h < 32) ? b1[h] : b2[hh]);
    }
}

// ============================================================================
// proj_mma: Xr[32768x256] @ W'[256x64] via mma, n-major row order (g_mr).
// CTA tile 128(M=one n, all s) x 64(N=h), 4 warps 2x2 of 64x32, K=8 chunks.
// Epilogue: val = (r*dot - mur*cw[h] + c2[h]) * mask, rna -> g_a/g_b.
// ============================================================================
__global__ void __launch_bounds__(128) proj_mma(const float* __restrict__ mask) {
    extern __shared__ __align__(16) float sm[];
    const uint32_t sbase = smem_u32(sm);
    const int tid = threadIdx.x, wid = tid >> 5, lane = tid & 31;
    const int wm = (wid & 1) * 64, wn = (wid >> 1) * 32;
    const int n = blockIdx.x;                 // fixed n per CTA; rows = s 0..127
    const int lg = lane >> 3, lrow = lane & 7;
    const uint32_t a_lo = (uint32_t)(wm + (lg & 1) * 8 + lrow) * ROW_BYTES
                        + (uint32_t)(lg >> 1) * 16;
    const uint32_t b_lo = PB_OFF + (uint32_t)(wn + (lg >> 1) * 8 + lrow) * ROW_BYTES
                        + (uint32_t)(lg & 1) * 16;
    const float* gAn = &g_mr[(size_t)n * S_DIM * CM];

    float acc[4][4][4];
    #pragma unroll
    for (int a = 0; a < 4; a++)
        #pragma unroll
        for (int b = 0; b < 4; b++)
            #pragma unroll
            for (int e = 0; e < 4; e++) acc[a][b][e] = 0.f;

    auto copy1 = [&](int ch, int st) {
        const int kb = ch * 32;
        const uint32_t dA = sbase + st * PSTAGE_BYTES;
        const uint32_t dB = dA + PB_OFF;
        #pragma unroll
        for (int i = 0; i < 8; i++) {         // A: 128 s-rows x 32 k (contiguous rows)
            int f = tid + i * 128, rr = f >> 3, cc = f & 7;
            cp16(dA + rr * ROW_BYTES + cc * 16, &gAn[rr * CM + kb + cc * 4]);
        }
        #pragma unroll
        for (int i = 0; i < 4; i++) {         // B: 64 h-rows x 32 k
            int f = tid + i * 128, rr = f >> 3, cc = f & 7;
            cp16_ca(dB + rr * ROW_BYTES + cc * 16,
                    &g_wpT[rr * CM + kb + cc * 4]);
        }
    };

    copy1(0, 0); CP_COMMIT();
    copy1(1, 1); CP_COMMIT();

    int st = 0;
    #pragma unroll 1
    for (int ch = 0; ch < 8; ch++) {
        CP_WAIT1();
        __syncthreads();
        const uint32_t so = sbase + (uint32_t)st * PSTAGE_BYTES;
        mma_chunk(so + a_lo, so + b_lo, acc);
        if (ch + 2 < 8) {
            int ns = st + 2; if (ns >= 3) ns -= 3;
            copy1(ch + 2, ns);
        }
        CP_COMMIT();
        if (++st == 3) st = 0;
    }

    // epilogue: per-row stats, per-col constants, mask, rna, scatter
    float* dst = (wn == 0) ? g_a : g_b;
    #pragma unroll
    for (int mt = 0; mt < 4; mt++) {
        const int s0 = wm + mt * 16 + (lane >> 2);
        const float2 st0 = g_stat2[n * S_DIM + s0];
        const float2 st1 = g_stat2[n * S_DIM + s0 + 8];
        const float mk0 = mask[s0 * N_DIM + n];
        const float mk1 = mask[(s0 + 8) * N_DIM + n];
        #pragma unroll
        for (int nt = 0; nt < 4; nt++) {
            const int h = wn + nt * 8 + (lane & 3) * 2;
            const int hh = h & 31;
            const float cwa = g_cw[h], cwb = g_cw[h + 1];
            const float c2a = g_c2[h], c2b = g_c2[h + 1];
            float* d0 = &dst[(size_t)(n * CH + hh) * S_DIM];
            float* d1 = d0 + S_DIM;
            d0[s0]     = __uint_as_float(rna_tf32((st0.x * acc[mt][nt][0] - st0.y * cwa + c2a) * mk0));
            d1[s0]     = __uint_as_float(rna_tf32((st0.x * acc[mt][nt][1] - st0.y * cwb + c2b) * mk0));
            d0[s0 + 8] = __uint_as_float(rna_tf32((st1.x * acc[mt][nt][2] - st1.y * cwa + c2a) * mk1));
            d1[s0 + 8] = __uint_as_float(rna_tf32((st1.x * acc[mt][nt][3] - st1.y * cwb + c2b) * mk1));
        }
    }
}

// ============================================================================
// norm + woT
// ============================================================================
__global__ void norm_kernel(const float* __restrict__ mask) {
    const int i = blockIdx.x, j = threadIdx.x;
    __shared__ float mi[S_DIM];
    if (j < S_DIM) mi[j] = mask[j * N_DIM + i];
    __syncthreads();
    float acc = 0.f;
    #pragma unroll 8
    for (int s = 0; s < S_DIM; s++) acc += mi[s] * mask[s * N_DIM + j];
    g_norm[i * N_DIM + j] = acc + OPM_EPS;
}

__global__ void woT_kernel(const float* __restrict__ wo) {
    int idx = blockIdx.x * 256 + threadIdx.x;   // 131072
    int z = idx >> 10, k = idx & 1023;
    g_woT[idx] = __uint_as_float(rna_tf32(wo[k * CZ + z]));
}

// ============================================================================
// GEMM1: O[8192,8192] = A[8192,128]*B[8192,128]^T.  128x128 CTA, 8 warps
// (2M x 4N) of 64x32, cp.async 3-stage pipeline, NC=4 chunks, 2 CTAs/SM.
// ============================================================================
__global__ void __launch_bounds__(256, 2) gemm1_mma() {
    extern __shared__ __align__(16) float sm[];
    const uint32_t sbase = smem_u32(sm);
    const int tid = threadIdx.x, wid = tid >> 5, lane = tid & 31;
    const int wm = (wid & 1) * 64, wn = (wid >> 1) * 32;
    const int p0 = blockIdx.y * 128, q0 = blockIdx.x * 128;
    const int lg = lane >> 3, lrow = lane & 7;
    const uint32_t a_lo = (uint32_t)(wm + (lg & 1) * 8 + lrow) * ROW_BYTES
                        + (uint32_t)(lg >> 1) * 16;
    const uint32_t b_lo = B_OFF + (uint32_t)(wn + (lg >> 1) * 8 + lrow) * ROW_BYTES
                        + (uint32_t)(lg & 1) * 16;

    float acc[4][4][4];
    #pragma unroll
    for (int a = 0; a < 4; a++)
        #pragma unroll
        for (int b = 0; b < 4; b++)
            #pragma unroll
            for (int e = 0; e < 4; e++) acc[a][b][e] = 0.f;

    auto copy1 = [&](int ch, int st) {
        const int kb = ch * 32;
        const uint32_t dA = sbase + st * STAGE_BYTES;
        const uint32_t dB = dA + B_OFF;
        #pragma unroll
        for (int i = 0; i < 4; i++) {
            int f = tid + i * 256, rr = f >> 3, cc = f & 7;
            cp16(dA + rr * ROW_BYTES + cc * 16,
                 &g_a[(size_t)(p0 + rr) * S_DIM + kb + cc * 4]);
            cp16(dB + rr * ROW_BYTES + cc * 16,
                 &g_b[(size_t)(q0 + rr) * S_DIM + kb + cc * 4]);
        }
    };

    copy1(0, 0); CP_COMMIT();
    copy1(1, 1); CP_COMMIT();

    #pragma unroll
    for (int ch = 0; ch < 4; ch++) {
        CP_WAIT1();
        __syncthreads();
        const uint32_t so = sbase + (uint32_t)(ch % 3) * STAGE_BYTES;
        mma_chunk(so + a_lo, so + b_lo, acc);
        if (ch + 2 < 4) copy1(ch + 2, (ch + 2) % 3);
        CP_COMMIT();
    }

    // epilogue -> g_O (tf32-rounded)
    #pragma unroll
    for (int mt = 0; mt < 4; mt++) {
        const int row0 = p0 + wm + mt * 16 + (lane >> 2);
        #pragma unroll
        for (int nt = 0; nt < 4; nt++) {
            const int col = q0 + wn + nt * 8 + (lane & 3) * 2;
            float2 v0, v1;
            v0.x = __uint_as_float(rna_tf32(acc[mt][nt][0]));
            v0.y = __uint_as_float(rna_tf32(acc[mt][nt][1]));
            v1.x = __uint_as_float(rna_tf32(acc[mt][nt][2]));
            v1.y = __uint_as_float(rna_tf32(acc[mt][nt][3]));
            *(float2*)&g_O[(size_t)row0 * P_DIM + col]       = v0;
            *(float2*)&g_O[(size_t)(row0 + 8) * P_DIM + col] = v1;
        }
    }
}

// ============================================================================
// GEMM2: out[65536,128] = O'[65536,1024] @ woT^T (+bo, /norm).
// 128x128 CTA, 8 warps (2M x 4N) of 64x32, cp.async 3-stage, NC=32 chunks.
// CTA order REVERSED so first reads hit gemm1's freshly-written (L2-resident) O.
// ============================================================================
__global__ void __launch_bounds__(256, 2) gemm2_mma(const float* __restrict__ bo,
                                                    float* __restrict__ out) {
    extern __shared__ __align__(16) float sm[];
    const uint32_t sbase = smem_u32(sm);
    const int tid = threadIdx.x, wid = tid >> 5, lane = tid & 31;
    const int wm = (wid & 1) * 64, wn = (wid >> 1) * 32;
    const int bid = (int)gridDim.x - 1 - (int)blockIdx.x;   // reversed
    const int m0 = bid * 128;
    const int i_idx = m0 >> 8, j0 = m0 & 255;
    const int lg = lane >> 3, lrow = lane & 7;
    const uint32_t a_lo = (uint32_t)(wm + (lg & 1) * 8 + lrow) * ROW_BYTES
                        + (uint32_t)(lg >> 1) * 16;
    const uint32_t b_lo = B_OFF + (uint32_t)(wn + (lg >> 1) * 8 + lrow) * ROW_BYTES
                        + (uint32_t)(lg & 1) * 16;

    float acc[4][4][4];
    #pragma unroll
    for (int a = 0; a < 4; a++)
        #pragma unroll
        for (int b = 0; b < 4; b++)
            #pragma unroll
            for (int e = 0; e < 4; e++) acc[a][b][e] = 0.f;

    auto copy1 = [&](int ch, int st) {
        const float* gA = &g_O[((size_t)(i_idx * 32 + ch)) * P_DIM + (size_t)j0 * 32];
        const uint32_t dA = sbase + st * STAGE_BYTES;
        const uint32_t dB = dA + B_OFF;
        #pragma unroll
        for (int i = 0; i < 4; i++) {
            int f = tid + i * 256, rr = f >> 3, cc = f & 7;
            cp16(dA + rr * ROW_BYTES + cc * 16, &gA[f * 4]);
            cp16_ca(dB + rr * ROW_BYTES + cc * 16,
                    &g_woT[(size_t)rr * 1024 + ch * 32 + cc * 4]);
        }
    };

    copy1(0, 0); CP_COMMIT();
    copy1(1, 1); CP_COMMIT();

    int st = 0;
    for (int ch = 0; ch < 32; ch++) {
        CP_WAIT1();
        __syncthreads();
        const uint32_t so = sbase + (uint32_t)st * STAGE_BYTES;
        mma_chunk(so + a_lo, so + b_lo, acc);
        if (ch + 2 < 32) {
            int ns = st + 2; if (ns >= 3) ns -= 3;
            copy1(ch + 2, ns);
        }
        CP_COMMIT();
        if (++st == 3) st = 0;
    }

    // epilogue: +bo, /norm
    #pragma unroll
    for (int mt = 0; mt < 4; mt++) {
        const int row0 = m0 + wm + mt * 16 + (lane >> 2);
        const float inv0 = 1.0f / g_norm[row0];
        const float inv1 = 1.0f / g_norm[row0 + 8];
        #pragma unroll
        for (int nt = 0; nt < 4; nt++) {
            const int col = wn + nt * 8 + (lane & 3) * 2;
            const float b0v = bo[col], b1v = bo[col + 1];
            float2 v0, v1;
            v0.x = (acc[mt][nt][0] + b0v) * inv0;
            v0.y = (acc[mt][nt][1] + b1v) * inv0;
            v1.x = (acc[mt][nt][2] + b0v) * inv1;
            v1.y = (acc[mt][nt][3] + b1v) * inv1;
            *(float2*)&out[(size_t)row0 * CZ + col]       = v0;
            *(float2*)&out[(size_t)(row0 + 8) * CZ + col] = v1;
        }
    }
}

// ============================================================================
extern "C" void kernel_launch(void* const* d_in, const int* in_sizes, int n_in,
                              void* d_out, int out_size) {
    const float* m    = (const float*)d_in[0];
    const float* mask = (const float*)d_in[1];
    const float* ln_w = (const float*)d_in[2];
    const float* ln_b = (const float*)d_in[3];
    const float* w1   = (const float*)d_in[4];
    const float* b1   = (const float*)d_in[5];
    const float* w2   = (const float*)d_in[6];
    const float* b2   = (const float*)d_in[7];
    const float* wo   = (const float*)d_in[8];
    const float* bo   = (const float*)d_in[9];
    float* out = (float*)d_out;

    cudaFuncSetAttribute(proj_mma, cudaFuncAttributeMaxDynamicSharedMemorySize, PSMEM_BYTES);
    cudaFuncSetAttribute(gemm1_mma, cudaFuncAttributeMaxDynamicSharedMemorySize, SMEM_BYTES);
    cudaFuncSetAttribute(gemm2_mma, cudaFuncAttributeMaxDynamicSharedMemorySize, SMEM_BYTES);

    stats_kernel<<<4096, 256>>>(m);
    prep_kernel<<<1, 256>>>(w1, b1, w2, b2, ln_w, ln_b);
    norm_kernel<<<N_DIM, 256>>>(mask);
    woT_kernel<<<512, 256>>>(wo);

    proj_mma<<<256, 128, PSMEM_BYTES>>>(mask);

    dim3 g1(64, 64);
    gemm1_mma<<<g1, 256, SMEM_BYTES>>>();
    gemm2_mma<<<512, 256, SMEM_BYTES>>>(bo, out);
}